// round 13
// baseline (speedup 1.0000x reference)
#include <cuda_runtime.h>
#include <math.h>
#include <stdint.h>

#define BATCH  256
#define DIM    512
#define NCLS   100000
#define MROWS  300000
#define BM     144                 // weight rows per tile = 48 classes
#define NT     2084                // ceil(300000/144)
#define KCH    64                  // int8 elements per k-chunk
#define NCHUNK 8                   // 512/64
#define FBLK   64                  // reduction blocks

// ArcFace constants (margin = 0.5)
#define COS_M 0.8775825618903728f
#define SIN_M 0.479425538604203f
#define TH_C  (-0.8775825618903728f)
#define MM_C  0.2397127693021015f

// smem stage layout (bytes): W | E, padded rows of 80B (64B data + 16 pad)
#define WH_OFF 0
#define EH_OFF 11520               // 144*80
#define STAGE  32000               // + 256*80
#define CPAD   264                 // epilogue C row stride (floats)
#define SMEM_DYN (BM * CPAD * 4)   // 152064 >= 2*STAGE=64000

#define CP_ASYNC16(dst, src) \
    asm volatile("cp.async.cg.shared.global [%0], [%1], 16;" :: "r"(dst), "l"(src) : "memory")
#define CP_COMMIT() asm volatile("cp.async.commit_group;" ::: "memory")
#define CP_WAIT0()  asm volatile("cp.async.wait_group 0;" ::: "memory")

#define LDSM_X4(r, a) \
    asm volatile("ldmatrix.sync.aligned.m8n8.x4.shared.b16 {%0,%1,%2,%3}, [%4];" \
        : "=r"((r)[0]), "=r"((r)[1]), "=r"((r)[2]), "=r"((r)[3]) : "r"(a))

// s8 x s8 -> s32 accumulate, K=32
static __device__ __forceinline__ void mma16832i(int* d, const uint32_t* a, const uint32_t* b) {
    asm volatile("mma.sync.aligned.m16n8k32.row.col.s32.s8.s8.s32 "
                 "{%0,%1,%2,%3}, {%4,%5,%6,%7}, {%8,%9}, {%0,%1,%2,%3};"
                 : "+r"(d[0]), "+r"(d[1]), "+r"(d[2]), "+r"(d[3])
                 : "r"(a[0]), "r"(a[1]), "r"(a[2]), "r"(a[3]), "r"(b[0]), "r"(b[1]));
}

static __device__ __forceinline__ int q8(float x, float s) {
    int q = __float2int_rn(x * s);
    return min(max(q, -127), 127);
}

// ---------------- scratch ----------------
__device__ __align__(16) uint32_t g_E8[BATCH * DIM / 4];   // int8 packed
__device__ float g_sE[BATCH];
__device__ float g_ps[(size_t)NT * BATCH];
__device__ float g_ps2[FBLK * BATCH];
__device__ float g_lab[BATCH];
__device__ int   g_labels[BATCH];

// ---------------- normalize embeddings -> int8; block 0 decodes labels ----
__global__ void k_prep(const float* __restrict__ emb, const int* __restrict__ lb) {
    int n = blockIdx.x, tid = threadIdx.x;   // 128 threads, 4 contiguous elems
    if (n == 0) {
        __shared__ int any_nz;
        if (tid == 0) any_nz = 0;
        __syncthreads();
        if (lb[2 * tid + 1] != 0) any_nz = 1;
        __syncthreads();
        g_labels[tid] = any_nz ? lb[tid] : lb[2 * tid];
        g_labels[tid + 128] = any_nz ? lb[tid + 128] : lb[2 * (tid + 128)];
    }
    float4 q = ((const float4*)emb)[n * 128 + tid];
    float ss = q.x * q.x + q.y * q.y + q.z * q.z + q.w * q.w;
#pragma unroll
    for (int o = 16; o; o >>= 1) ss += __shfl_xor_sync(0xffffffffu, ss, o);
    __shared__ float sw[4], sm[4];
    __shared__ float sinv, smax;
    if ((tid & 31) == 0) sw[tid >> 5] = ss;
    __syncthreads();
    if (tid == 0) sinv = 1.f / fmaxf(sqrtf(sw[0] + sw[1] + sw[2] + sw[3]), 1e-12f);
    __syncthreads();
    float inv = sinv;
    float x0 = q.x * inv, x1 = q.y * inv, x2 = q.z * inv, x3 = q.w * inv;
    float m = fmaxf(fmaxf(fabsf(x0), fabsf(x1)), fmaxf(fabsf(x2), fabsf(x3)));
#pragma unroll
    for (int o = 16; o; o >>= 1) m = fmaxf(m, __shfl_xor_sync(0xffffffffu, m, o));
    if ((tid & 31) == 0) sm[tid >> 5] = m;
    __syncthreads();
    if (tid == 0) {
        float mm = fmaxf(fmaxf(sm[0], sm[1]), fmaxf(sm[2], sm[3]));
        smax = mm;
        g_sE[n] = mm / 127.f;
    }
    __syncthreads();
    float invs = (smax > 0.f) ? 127.f / smax : 0.f;
    int q0 = q8(x0, invs), q1 = q8(x1, invs), q2 = q8(x2, invs), q3 = q8(x3, invs);
    g_E8[n * 128 + tid] = (uint32_t)(q0 & 0xFF) | ((uint32_t)(q1 & 0xFF) << 8) |
                          ((uint32_t)(q2 & 0xFF) << 16) | ((uint32_t)(q3 & 0xFF) << 24);
}

// ---------------- fused: int8 MMA GEMM + wnorm + max3 + softmax ------------
__global__ void __launch_bounds__(384, 1) k_gemm(const float* __restrict__ W) {
    extern __shared__ char smem[];
    __shared__ float s_inv[BM];
    int t = threadIdx.x;
    int lane = t & 31, warp = t >> 5;
    int warpM = warp % 3, warpN = warp / 3;     // 3M x 4N warp grid

    float invSW = 127.f / sqrtf(6.f / 300512.f);
    float sW = sqrtf(6.f / 300512.f) / 127.f;

    size_t wbase = (size_t)blockIdx.x * BM;
    float ssq[6] = {0.f, 0.f, 0.f, 0.f, 0.f, 0.f};
    int acc[3][8][4];
#pragma unroll
    for (int i = 0; i < 3; i++)
#pragma unroll
        for (int j = 0; j < 8; j++)
#pragma unroll
            for (int k = 0; k < 4; k++) acc[i][j][k] = 0;

    uint32_t sbase = (uint32_t)__cvta_generic_to_shared(smem);

    // ldmatrix per-lane row offsets (g = lane>>3 selects the 8x8 matrix slot)
    int g = lane >> 3, lr = lane & 7;
    uint32_t b_row_off = (uint32_t)((warpN * 64 + ((g >> 1) << 3) + lr) * 80 + (g & 1) * 16);
    uint32_t a_row_off = (uint32_t)((warpM * 48 + ((g & 1) << 3) + lr) * 80 + (g >> 1) * 16);

    const char* E8 = (const char*)g_E8;

    // ---- prologue: chunk 0 into stage 0 ----
    {
        float4 wreg[6];
#pragma unroll
        for (int j = 0; j < 6; j++) {
            int i = t + 384 * j, row = i >> 4, c16 = i & 15;
            size_t rg = wbase + row;
            wreg[j] = (rg < (size_t)MROWS) ? *(const float4*)(W + rg * DIM + c16 * 4)
                                           : make_float4(0.f, 0.f, 0.f, 0.f);
        }
#pragma unroll
        for (int i = 0; i < 3; i++) {
            int j = t + 384 * i;
            if (j < 1024) {
                int r = j >> 2, seg = j & 3;
                CP_ASYNC16(sbase + EH_OFF + r * 80 + seg * 16, E8 + r * DIM + seg * 16);
            }
        }
        CP_COMMIT();
#pragma unroll
        for (int j = 0; j < 6; j++) {
            int i = t + 384 * j, row = i >> 4, c16 = i & 15;
            float4 q = wreg[j];
            ssq[j] = fmaf(q.x, q.x, fmaf(q.y, q.y, fmaf(q.z, q.z, fmaf(q.w, q.w, ssq[j]))));
            int q0 = q8(q.x, invSW), q1 = q8(q.y, invSW), q2 = q8(q.z, invSW), q3 = q8(q.w, invSW);
            *(uint32_t*)(smem + WH_OFF + row * 80 + c16 * 4) =
                (uint32_t)(q0 & 0xFF) | ((uint32_t)(q1 & 0xFF) << 8) |
                ((uint32_t)(q2 & 0xFF) << 16) | ((uint32_t)(q3 & 0xFF) << 24);
        }
        CP_WAIT0();
        __syncthreads();
    }

    // ---- mainloop ----
    for (int c = 0; c < NCHUNK; c++) {
        uint32_t sb_cur = sbase + (c & 1) * STAGE;
        char* nxt = smem + ((c + 1) & 1) * STAGE;
        uint32_t nxt_s = sbase + ((c + 1) & 1) * STAGE;
        float4 wreg[6];
        if (c + 1 < NCHUNK) {
#pragma unroll
            for (int j = 0; j < 6; j++) {
                int i = t + 384 * j, row = i >> 4, c16 = i & 15;
                size_t rg = wbase + row;
                wreg[j] = (rg < (size_t)MROWS)
                              ? *(const float4*)(W + rg * DIM + (c + 1) * KCH + c16 * 4)
                              : make_float4(0.f, 0.f, 0.f, 0.f);
            }
#pragma unroll
            for (int i = 0; i < 3; i++) {
                int j = t + 384 * i;
                if (j < 1024) {
                    int r = j >> 2, seg = j & 3;
                    CP_ASYNC16(nxt_s + EH_OFF + r * 80 + seg * 16,
                               E8 + r * DIM + (c + 1) * KCH + seg * 16);
                }
            }
            CP_COMMIT();
        }

        // compute chunk c: 2 k-steps (32 int8 each)
#pragma unroll
        for (int ks = 0; ks < 2; ks++) {
            uint32_t Wb = sb_cur + WH_OFF + ks * 32;
            uint32_t Eb = sb_cur + EH_OFF + ks * 32;
            uint32_t bfr[4][4];
#pragma unroll
            for (int pr = 0; pr < 4; pr++)
                LDSM_X4(bfr[pr], Eb + b_row_off + pr * (16 * 80));
#pragma unroll
            for (int mt = 0; mt < 3; mt++) {
                uint32_t af[4];
                LDSM_X4(af, Wb + a_row_off + mt * (16 * 80));
#pragma unroll
                for (int nt = 0; nt < 8; nt++) {
                    uint32_t bb[2] = { bfr[nt >> 1][(nt & 1) * 2],
                                       bfr[nt >> 1][(nt & 1) * 2 + 1] };
                    mma16832i(acc[mt][nt], af, bb);
                }
            }
        }

        if (c + 1 < NCHUNK) {
#pragma unroll
            for (int j = 0; j < 6; j++) {
                int i = t + 384 * j, row = i >> 4, c16 = i & 15;
                float4 q = wreg[j];
                ssq[j] = fmaf(q.x, q.x, fmaf(q.y, q.y, fmaf(q.z, q.z, fmaf(q.w, q.w, ssq[j]))));
                int q0 = q8(q.x, invSW), q1 = q8(q.y, invSW), q2 = q8(q.z, invSW), q3 = q8(q.w, invSW);
                *(uint32_t*)(nxt + WH_OFF + row * 80 + c16 * 4) =
                    (uint32_t)(q0 & 0xFF) | ((uint32_t)(q1 & 0xFF) << 8) |
                    ((uint32_t)(q2 & 0xFF) << 16) | ((uint32_t)(q3 & 0xFF) << 24);
            }
            CP_WAIT0();
        }
        __syncthreads();
    }

    // ---- weight inv-norms: 16 threads share a row ----
#pragma unroll
    for (int j = 0; j < 6; j++) {
        float v = ssq[j];
        v += __shfl_xor_sync(0xffffffffu, v, 8);
        v += __shfl_xor_sync(0xffffffffu, v, 4);
        v += __shfl_xor_sync(0xffffffffu, v, 2);
        v += __shfl_xor_sync(0xffffffffu, v, 1);
        if ((t & 15) == 0) s_inv[(t + 384 * j) >> 4] = sW / fmaxf(sqrtf(v), 1e-12f);
    }

    // ---- dump acc to smem C (aliases stages; all compute done) ----
    float* C = (float*)smem;
#pragma unroll
    for (int mt = 0; mt < 3; mt++)
#pragma unroll
        for (int nt = 0; nt < 8; nt++) {
            int rr = warpM * 48 + mt * 16 + (lane >> 2);
            int cc = warpN * 64 + nt * 8 + 2 * (lane & 3);
            *(float2*)&C[rr * CPAD + cc] =
                make_float2((float)acc[mt][nt][0], (float)acc[mt][nt][1]);
            *(float2*)&C[(rr + 8) * CPAD + cc] =
                make_float2((float)acc[mt][nt][2], (float)acc[mt][nt][3]);
        }
    __syncthreads();

    // ---- fused epilogue: per-thread batch column ----
    if (t < BATCH) {
        int n = t;
        int lab = g_labels[n];
        float se = g_sE[n];
        int cls0 = blockIdx.x * 48;
        float ssum = 0.f;
#pragma unroll 4
        for (int cl = 0; cl < 48; cl++) {
            int r = cl * 3;
            float c0 = C[r * CPAD + n] * s_inv[r] * se;
            float c1 = C[(r + 1) * CPAD + n] * s_inv[r + 1] * se;
            float c2 = C[(r + 2) * CPAD + n] * s_inv[r + 2] * se;
            float cm = fmaxf(c0, fmaxf(c1, c2));
            int gc = cls0 + cl;
            if (gc < NCLS) {
                float x;
                if (gc == lab) {
                    float sine = sqrtf(fminf(fmaxf(1.f - cm * cm, 0.f), 1.f));
                    float phi = cm * COS_M - sine * SIN_M;
                    if (!(cm > TH_C)) phi = cm - MM_C;
                    x = 64.f * phi;
                    g_lab[n] = x;
                } else {
                    x = 64.f * cm;
                }
                ssum += __expf(x - 64.f);
            }
        }
        g_ps[(size_t)blockIdx.x * BATCH + n] = ssum;
    }
}

// ---------------- two-stage reduction ----------------
__global__ void k_part(void) {
    int t = threadIdx.x, b = blockIdx.x;   // FBLK blocks x 256 threads
    int k0 = b * 33, k1 = k0 + 33;
    if (k1 > NT) k1 = NT;
    float s = 0.f;
    for (int k = k0; k < k1; k++) s += g_ps[(size_t)k * BATCH + t];
    g_ps2[b * BATCH + t] = s;
}

__global__ void k_final(float* __restrict__ out) {
    int t = threadIdx.x;  // 256
    float s = 0.f;
#pragma unroll 8
    for (int k = 0; k < FBLK; k++) s += g_ps2[k * BATCH + t];
    float loss = 64.f + logf(s) - g_lab[t];
#pragma unroll
    for (int o = 16; o; o >>= 1) loss += __shfl_xor_sync(0xffffffffu, loss, o);
    __shared__ float sw[8];
    if ((t & 31) == 0) sw[t >> 5] = loss;
    __syncthreads();
    if (t == 0) {
        float tot = 0.f;
#pragma unroll
        for (int i = 0; i < 8; i++) tot += sw[i];
        out[0] = tot / (float)BATCH;
    }
}

// ---------------------------------------------------------------------------
extern "C" void kernel_launch(void* const* d_in, const int* in_sizes, int n_in,
                              void* d_out, int out_size) {
    const float* emb    = (const float*)d_in[0];
    const int*   labels = (const int*)d_in[1];
    const float* W      = (const float*)d_in[2];

    cudaFuncSetAttribute(k_gemm, cudaFuncAttributeMaxDynamicSharedMemorySize, SMEM_DYN);

    k_prep<<<BATCH, 128>>>(emb, labels);
    k_gemm<<<NT, 384, SMEM_DYN>>>(W);
    k_part<<<FBLK, BATCH>>>();
    k_final<<<1, BATCH>>>((float*)d_out);
}

// round 14
// speedup vs baseline: 1.7127x; 1.7127x over previous
#include <cuda_runtime.h>
#include <cuda_bf16.h>
#include <math.h>
#include <stdint.h>

#define BATCH  256
#define DIM    512
#define NCLS   100000
#define MROWS  300000
#define BM     96                  // weight rows per tile = 32 classes (exact: 3125 tiles)
#define NT     3125                // 300000/96 exactly
#define KCH    32
#define NCHUNK 16                  // 512/32
#define FBLK   64                  // reduction blocks

// ArcFace constants (margin = 0.5)
#define COS_M 0.8775825618903728f
#define SIN_M 0.479425538604203f
#define TH_C  (-0.8775825618903728f)
#define MM_C  0.2397127693021015f

// smem stage layout (bytes): Wh | Eh, padded rows of 80B (40 halfs)
#define WH_OFF 0
#define EH_OFF 7680                // 96*80
#define STAGE  28160               // + 256*80
#define CPAD   264                 // epilogue C row stride (floats)
#define SMEM_DYN (BM * CPAD * 4)   // 101376 >= 2*STAGE=56320

#define CP_ASYNC16(dst, src) \
    asm volatile("cp.async.cg.shared.global [%0], [%1], 16;" :: "r"(dst), "l"(src) : "memory")
#define CP_COMMIT() asm volatile("cp.async.commit_group;" ::: "memory")
#define CP_WAIT0()  asm volatile("cp.async.wait_group 0;" ::: "memory")

#define LDSM_X4(r, a) \
    asm volatile("ldmatrix.sync.aligned.m8n8.x4.shared.b16 {%0,%1,%2,%3}, [%4];" \
        : "=r"((r)[0]), "=r"((r)[1]), "=r"((r)[2]), "=r"((r)[3]) : "r"(a))

static __device__ __forceinline__ void mma16816(float* d, const uint32_t* a, const uint32_t* b) {
    asm volatile("mma.sync.aligned.m16n8k16.row.col.f32.bf16.bf16.f32 "
                 "{%0,%1,%2,%3}, {%4,%5,%6,%7}, {%8,%9}, {%0,%1,%2,%3};"
                 : "+f"(d[0]), "+f"(d[1]), "+f"(d[2]), "+f"(d[3])
                 : "r"(a[0]), "r"(a[1]), "r"(a[2]), "r"(a[3]), "r"(b[0]), "r"(b[1]));
}

// ---------------- scratch ----------------
__device__ __align__(16) __nv_bfloat16 g_Ehi[BATCH * DIM];
__device__ float g_ps[(size_t)NT * BATCH];
__device__ float g_ps2[FBLK * BATCH];
__device__ float g_lab[BATCH];
__device__ int   g_labels[BATCH];

// ---------------- normalize embeddings -> bf16; block 0 decodes labels ----
__global__ void k_prep(const float* __restrict__ emb, const int* __restrict__ lb) {
    int n = blockIdx.x, tid = threadIdx.x;   // 128 threads
    if (n == 0) {
        __shared__ int any_nz;
        if (tid == 0) any_nz = 0;
        __syncthreads();
        if (lb[2 * tid + 1] != 0) any_nz = 1;
        __syncthreads();
        g_labels[tid] = any_nz ? lb[tid] : lb[2 * tid];
        g_labels[tid + 128] = any_nz ? lb[tid + 128] : lb[2 * (tid + 128)];
    }
    float v[4], ss = 0.f;
#pragma unroll
    for (int i = 0; i < 4; i++) {
        v[i] = emb[n * DIM + tid + i * 128];
        ss += v[i] * v[i];
    }
#pragma unroll
    for (int o = 16; o; o >>= 1) ss += __shfl_xor_sync(0xffffffffu, ss, o);
    __shared__ float sw[4];
    __shared__ float sinv;
    if ((tid & 31) == 0) sw[tid >> 5] = ss;
    __syncthreads();
    if (tid == 0) sinv = 1.f / fmaxf(sqrtf(sw[0] + sw[1] + sw[2] + sw[3]), 1e-12f);
    __syncthreads();
    float inv = sinv;
#pragma unroll
    for (int i = 0; i < 4; i++)
        g_Ehi[n * DIM + tid + i * 128] = __float2bfloat16(v[i] * inv);
}

// ---------------- fused: bf16 MMA GEMM + wnorm + max3 + softmax ------------
__global__ void __launch_bounds__(256, 2) k_gemm(const float* __restrict__ W) {
    extern __shared__ char smem[];
    __shared__ float s_inv[BM];
    int t = threadIdx.x;
    int lane = t & 31, warp = t >> 5;
    int warpM = warp & 1, warpN = warp >> 1;    // 2M x 4N warp grid (48x64 tiles)

    size_t wbase = (size_t)blockIdx.x * BM;
    float ssq[3] = {0.f, 0.f, 0.f};
    float acc[3][8][4];
#pragma unroll
    for (int i = 0; i < 3; i++)
#pragma unroll
        for (int j = 0; j < 8; j++)
#pragma unroll
            for (int k = 0; k < 4; k++) acc[i][j][k] = 0.f;

    uint32_t sbase = (uint32_t)__cvta_generic_to_shared(smem);

    // ldmatrix per-lane row offsets (g = lane>>3 selects the 8x8 matrix slot)
    int g = lane >> 3, lr = lane & 7;
    uint32_t b_row_off = (uint32_t)((warpN * 64 + ((g >> 1) << 3) + lr) * 80 + (g & 1) * 16);
    uint32_t a_row_off = (uint32_t)((warpM * 48 + ((g & 1) << 3) + lr) * 80 + (g >> 1) * 16);

    // ---- prologue: chunk 0 into stage 0 ----
    {
        float4 wreg[3];
#pragma unroll
        for (int j = 0; j < 3; j++) {
            int i = t + 256 * j, row = i >> 3, c4 = i & 7;
            wreg[j] = *(const float4*)(W + (wbase + row) * DIM + c4 * 4);
        }
#pragma unroll
        for (int i = 0; i < 4; i++) {
            int j = t + 256 * i;
            int r = j >> 2, seg = j & 3;
            CP_ASYNC16(sbase + EH_OFF + r * 80 + seg * 16, g_Ehi + r * DIM + seg * 8);
        }
        CP_COMMIT();
#pragma unroll
        for (int j = 0; j < 3; j++) {
            int i = t + 256 * j, row = i >> 3, c4 = i & 7;
            float4 q = wreg[j];
            ssq[j] = fmaf(q.x, q.x, fmaf(q.y, q.y, fmaf(q.z, q.z, fmaf(q.w, q.w, ssq[j]))));
            __nv_bfloat162 h0 = __floats2bfloat162_rn(q.x, q.y);
            __nv_bfloat162 h1 = __floats2bfloat162_rn(q.z, q.w);
            uint2 uh;
            uh.x = *(uint32_t*)&h0; uh.y = *(uint32_t*)&h1;
            *(uint2*)(smem + WH_OFF + row * 80 + c4 * 8) = uh;
        }
        CP_WAIT0();
        __syncthreads();
    }

    // ---- mainloop ----
    for (int c = 0; c < NCHUNK; c++) {
        uint32_t sb_cur = sbase + (c & 1) * STAGE;
        char* nxt = smem + ((c + 1) & 1) * STAGE;
        uint32_t nxt_s = sbase + ((c + 1) & 1) * STAGE;
        float4 wreg[3];
        if (c + 1 < NCHUNK) {
#pragma unroll
            for (int j = 0; j < 3; j++) {
                int i = t + 256 * j, row = i >> 3, c4 = i & 7;
                wreg[j] = *(const float4*)(W + (wbase + row) * DIM + (c + 1) * KCH + c4 * 4);
            }
#pragma unroll
            for (int i = 0; i < 4; i++) {
                int j = t + 256 * i;
                int r = j >> 2, seg = j & 3;
                CP_ASYNC16(nxt_s + EH_OFF + r * 80 + seg * 16,
                           g_Ehi + r * DIM + (c + 1) * KCH + seg * 8);
            }
            CP_COMMIT();
        }

        // compute chunk c: 2 k-steps, single bf16 pass
#pragma unroll
        for (int ks = 0; ks < 2; ks++) {
            uint32_t Wb = sb_cur + WH_OFF + ks * 32;
            uint32_t Eb = sb_cur + EH_OFF + ks * 32;
            uint32_t bfr[4][4];
#pragma unroll
            for (int pr = 0; pr < 4; pr++)
                LDSM_X4(bfr[pr], Eb + b_row_off + pr * (16 * 80));
#pragma unroll
            for (int mt = 0; mt < 3; mt++) {
                uint32_t af[4];
                LDSM_X4(af, Wb + a_row_off + mt * (16 * 80));
#pragma unroll
                for (int nt = 0; nt < 8; nt++) {
                    uint32_t bb[2] = { bfr[nt >> 1][(nt & 1) * 2],
                                       bfr[nt >> 1][(nt & 1) * 2 + 1] };
                    mma16816(acc[mt][nt], af, bb);
                }
            }
        }

        if (c + 1 < NCHUNK) {
#pragma unroll
            for (int j = 0; j < 3; j++) {
                int i = t + 256 * j, row = i >> 3, c4 = i & 7;
                float4 q = wreg[j];
                ssq[j] = fmaf(q.x, q.x, fmaf(q.y, q.y, fmaf(q.z, q.z, fmaf(q.w, q.w, ssq[j]))));
                __nv_bfloat162 h0 = __floats2bfloat162_rn(q.x, q.y);
                __nv_bfloat162 h1 = __floats2bfloat162_rn(q.z, q.w);
                uint2 uh;
                uh.x = *(uint32_t*)&h0; uh.y = *(uint32_t*)&h1;
                *(uint2*)(nxt + WH_OFF + row * 80 + c4 * 8) = uh;
            }
            CP_WAIT0();
        }
        __syncthreads();
    }

    // ---- weight inv-norms (8 threads share a row) ----
#pragma unroll
    for (int j = 0; j < 3; j++) {
        float v = ssq[j];
        v += __shfl_xor_sync(0xffffffffu, v, 4);
        v += __shfl_xor_sync(0xffffffffu, v, 2);
        v += __shfl_xor_sync(0xffffffffu, v, 1);
        if ((t & 7) == 0) s_inv[(t + 256 * j) >> 3] = 1.f / fmaxf(sqrtf(v), 1e-12f);
    }

    // ---- dump acc to smem C (aliases stages; all compute done) ----
    float* C = (float*)smem;
#pragma unroll
    for (int mt = 0; mt < 3; mt++)
#pragma unroll
        for (int nt = 0; nt < 8; nt++) {
            int rr = warpM * 48 + mt * 16 + (lane >> 2);
            int cc = warpN * 64 + nt * 8 + 2 * (lane & 3);
            *(float2*)&C[rr * CPAD + cc] = make_float2(acc[mt][nt][0], acc[mt][nt][1]);
            *(float2*)&C[(rr + 8) * CPAD + cc] = make_float2(acc[mt][nt][2], acc[mt][nt][3]);
        }
    __syncthreads();

    // ---- fused epilogue: per-thread batch column (32 classes/tile) ----
    {
        int n = t;
        int lab = g_labels[n];
        int cls0 = blockIdx.x * 32;
        float ssum = 0.f;
#pragma unroll 4
        for (int cl = 0; cl < 32; cl++) {
            int r = cl * 3;
            float c0 = C[r * CPAD + n] * s_inv[r];
            float c1 = C[(r + 1) * CPAD + n] * s_inv[r + 1];
            float c2 = C[(r + 2) * CPAD + n] * s_inv[r + 2];
            float cm = fmaxf(c0, fmaxf(c1, c2));
            int gc = cls0 + cl;
            float x;
            if (gc == lab) {
                float sine = sqrtf(fminf(fmaxf(1.f - cm * cm, 0.f), 1.f));
                float phi = cm * COS_M - sine * SIN_M;
                if (!(cm > TH_C)) phi = cm - MM_C;
                x = 64.f * phi;
                g_lab[n] = x;
            } else {
                x = 64.f * cm;
            }
            ssum += __expf(x - 64.f);
        }
        g_ps[(size_t)blockIdx.x * BATCH + n] = ssum;
    }
}

// ---------------- two-stage reduction ----------------
__global__ void k_part(void) {
    int t = threadIdx.x, b = blockIdx.x;   // FBLK blocks x 256 threads
    int k0 = b * 49, k1 = k0 + 49;         // 64*49 = 3136 >= 3125
    if (k1 > NT) k1 = NT;
    float s = 0.f;
    for (int k = k0; k < k1; k++) s += g_ps[(size_t)k * BATCH + t];
    g_ps2[b * BATCH + t] = s;
}

__global__ void k_final(float* __restrict__ out) {
    int t = threadIdx.x;  // 256
    float s = 0.f;
#pragma unroll 8
    for (int k = 0; k < FBLK; k++) s += g_ps2[k * BATCH + t];
    float loss = 64.f + logf(s) - g_lab[t];
#pragma unroll
    for (int o = 16; o; o >>= 1) loss += __shfl_xor_sync(0xffffffffu, loss, o);
    __shared__ float sw[8];
    if ((t & 31) == 0) sw[t >> 5] = loss;
    __syncthreads();
    if (t == 0) {
        float tot = 0.f;
#pragma unroll
        for (int i = 0; i < 8; i++) tot += sw[i];
        out[0] = tot / (float)BATCH;
    }
}

// ---------------------------------------------------------------------------
extern "C" void kernel_launch(void* const* d_in, const int* in_sizes, int n_in,
                              void* d_out, int out_size) {
    const float* emb    = (const float*)d_in[0];
    const int*   labels = (const int*)d_in[1];
    const float* W      = (const float*)d_in[2];

    cudaFuncSetAttribute(k_gemm, cudaFuncAttributeMaxDynamicSharedMemorySize, SMEM_DYN);

    k_prep<<<BATCH, 128>>>(emb, labels);
    k_gemm<<<NT, 256, SMEM_DYN>>>(W);
    k_part<<<FBLK, BATCH>>>();
    k_final<<<1, BATCH>>>((float*)d_out);
}